// round 3
// baseline (speedup 1.0000x reference)
#include <cuda_runtime.h>
#include <math.h>

#define NR 32768          // B*M*M = 32*32*32 rows
#define LH 128
#define NSTEPS 19         // K-1

// ---------------- scratch (static device globals; no allocation) -------------
__device__ float g_hid[NR * LH];      // hid conv output, flat [n][ci]
__device__ float g_hA[NR * LH];       // h ping
__device__ float g_hB[NR * LH];       // h pong
__device__ float g_c[NR * LH];        // c (in-place)
__device__ float g_wth0[9 * LH * LH]; // h0_w transposed [tap][ci][co]
__device__ float g_wtc0[9 * LH * LH]; // c0_w transposed [tap][ci][co]

// ---------------- weight transpose prep --------------------------------------
__global__ void prep_weights(const float* __restrict__ h0w,
                             const float* __restrict__ c0w) {
    int idx = blockIdx.x * 256 + threadIdx.x;   // idx = (tap*128+ci)*128+co
    if (idx >= 9 * LH * LH) return;
    int co  = idx & (LH - 1);
    int ci  = (idx >> 7) & (LH - 1);
    int tap = idx >> 14;
    int dy = tap / 3, dx = tap % 3;
    int src = ((co * LH + ci) * 3 + dy) * 3 + dx;
    g_wth0[idx] = h0w[src];
    g_wtc0[idx] = c0w[src];
}

// ---------------- initial hid conv: (design,goal) -> hid ----------------------
// hid_flat[n][co] with n = b*1024 + x*32 + y   (x = W index, y = H index)
__global__ __launch_bounds__(256) void hid_kernel(
    const float* __restrict__ design, const float* __restrict__ goal,
    const float* __restrict__ hid_w, const float* __restrict__ hid_b,
    float* __restrict__ out) {
    __shared__ float Xs[5][34][34];   // zero-padded input image
    __shared__ float Ws[128 * 45];
    __shared__ float Bs[128];
    int b = blockIdx.x;
    int tid = threadIdx.x;
    for (int i = tid; i < 5 * 34 * 34; i += 256) ((float*)Xs)[i] = 0.f;
    __syncthreads();
    for (int i = tid; i < 5 * 1024; i += 256) {
        int ci = i >> 10, y = (i >> 5) & 31, x = i & 31;
        float v = (ci < 4) ? design[((b * 4 + ci) * 32 + y) * 32 + x]
                           : goal[b * 1024 + y * 32 + x];
        Xs[ci][y + 1][x + 1] = v;
    }
    for (int i = tid; i < 128 * 45; i += 256) Ws[i] = hid_w[i];
    if (tid < 128) Bs[tid] = hid_b[tid];
    __syncthreads();
    for (int idx = tid; idx < 1024 * 128; idx += 256) {
        int co = idx & 127, p = idx >> 7;
        int x = p >> 5, y = p & 31;
        float s = Bs[co];
        const float* w = &Ws[co * 45];
#pragma unroll
        for (int ci = 0; ci < 5; ci++)
#pragma unroll
            for (int dy = 0; dy < 3; dy++)
#pragma unroll
                for (int dx = 0; dx < 3; dx++)
                    s += w[ci * 9 + dy * 3 + dx] * Xs[ci][y + dy][x + dx];
        out[(b * 1024 + p) * LH + co] = s;
    }
}

// ---------------- 3x3 conv as 9-tap GEMM (h0 / c0) ---------------------------
// out[n][co] = bias[co] + sum_taps sum_ci wt[tap][ci][co] * in[n+off(tap)][ci]
__global__ __launch_bounds__(256, 2) void conv_gemm_kernel(
    const float* __restrict__ in, const float* __restrict__ wt,
    const float* __restrict__ bias, float* __restrict__ out,
    float* __restrict__ out2) {
    __shared__ float As[128][33];
    __shared__ float Bsm[128][33];
    int n0 = blockIdx.x * 128;
    int tid = threadIdx.x;
    int tx = tid & 15, ty = tid >> 4;
    float acc[8][8];
#pragma unroll
    for (int i = 0; i < 8; i++)
#pragma unroll
        for (int j = 0; j < 8; j++) acc[i][j] = 0.f;

    for (int tap = 0; tap < 9; tap++) {
        int dy = tap / 3 - 1, dx = tap % 3 - 1;
        int off = dx * 32 + dy;
        for (int kc = 0; kc < LH; kc += 32) {
#pragma unroll
            for (int p = 0; p < 16; p++) {
                int i = tid + p * 256;
                int r = i >> 5, kk = i & 31;
                int n = n0 + r;
                int y = n & 31, x = (n >> 5) & 31;
                bool ok = ((unsigned)(y + dy) < 32u) && ((unsigned)(x + dx) < 32u);
                As[r][kk] = ok ? in[(n + off) * LH + kc + kk] : 0.f;
            }
#pragma unroll
            for (int p = 0; p < 16; p++) {
                int i = tid + p * 256;
                int kk = i >> 7, co = i & 127;
                Bsm[co][kk] = wt[(tap * LH + kc + kk) * LH + co];
            }
            __syncthreads();
#pragma unroll
            for (int kk = 0; kk < 32; kk++) {
                float a[8], bb[8];
#pragma unroll
                for (int ri = 0; ri < 8; ri++) a[ri] = As[ty * 8 + ri][kk];
#pragma unroll
                for (int j = 0; j < 8; j++) bb[j] = Bsm[tx + 16 * j][kk];
#pragma unroll
                for (int ri = 0; ri < 8; ri++)
#pragma unroll
                    for (int j = 0; j < 8; j++) acc[ri][j] += a[ri] * bb[j];
            }
            __syncthreads();
        }
    }
#pragma unroll
    for (int ri = 0; ri < 8; ri++) {
        int n = n0 + ty * 8 + ri;
#pragma unroll
        for (int j = 0; j < 8; j++) {
            int co = tx + 16 * j;
            float v = acc[ri][j] + bias[co];
            out[n * LH + co] = v;
            if (out2) out2[n * LH + co] = v;
        }
    }
}

// ---------------- fused: inp conv + gates GEMM + LSTM update -----------------
// Block tile: 128 rows x (4 gates x 32 channels). cb = channel chunk (0..3).
// inp[n] (the 128->1 3x3 conv on hprev) is computed in-block into smem.
__global__ __launch_bounds__(256, 2) void step_kernel(
    const float* __restrict__ hprev,
    const float* __restrict__ w_hh, const float* __restrict__ w_ih,
    const float* __restrict__ b_ih, const float* __restrict__ b_hh,
    const float* __restrict__ conv_w, const float* __restrict__ conv_b,
    float* __restrict__ c, float* __restrict__ hnext) {
    __shared__ float As[128][33];
    __shared__ float Bsm[128][33];
    __shared__ float Inps[128];
    int n0 = blockIdx.x * 128;
    int cb = blockIdx.y;
    int tid = threadIdx.x;
    int tx = tid & 15, ty = tid >> 4;

    // ---- compute inp for the block's 128 rows: 16 rows per warp (8 warps)
    {
        int warp = tid >> 5, lane = tid & 31;
#pragma unroll
        for (int rr = 0; rr < 16; rr++) {
            int r = warp * 16 + rr;
            int n = n0 + r;
            int y = n & 31, x = (n >> 5) & 31;
            float s = 0.f;
#pragma unroll
            for (int dy = 0; dy < 3; dy++)
#pragma unroll
                for (int dx = 0; dx < 3; dx++) {
                    int yy = y + dy - 1, xx = x + dx - 1;
                    if ((unsigned)yy < 32u && (unsigned)xx < 32u) {
                        const float* row = hprev + (n + (dx - 1) * 32 + (dy - 1)) * LH;
#pragma unroll
                        for (int q = 0; q < 4; q++) {
                            int ch = lane + q * 32;
                            s += conv_w[ch * 9 + dy * 3 + dx] * row[ch];
                        }
                    }
                }
#pragma unroll
            for (int off = 16; off; off >>= 1)
                s += __shfl_xor_sync(0xffffffffu, s, off);
            if (lane == 0) Inps[r] = s + conv_b[0];
        }
    }

    float acc[8][8];
#pragma unroll
    for (int i = 0; i < 8; i++)
#pragma unroll
        for (int j = 0; j < 8; j++) acc[i][j] = 0.f;

    for (int kc = 0; kc < LH; kc += 32) {
#pragma unroll
        for (int p = 0; p < 16; p++) {
            int i = tid + p * 256;
            int r = i >> 5, kk = i & 31;
            As[r][kk] = hprev[(n0 + r) * LH + kc + kk];
        }
#pragma unroll
        for (int p = 0; p < 16; p++) {
            int i = tid + p * 256;
            int jj = i >> 5, kk = i & 31;       // jj = gate*32 + c_loc
            int j = (jj >> 5) * 128 + cb * 32 + (jj & 31);
            Bsm[jj][kk] = w_hh[j * LH + kc + kk];
        }
        __syncthreads();
#pragma unroll
        for (int kk = 0; kk < 32; kk++) {
            float a[8], bb[8];
#pragma unroll
            for (int ri = 0; ri < 8; ri++) a[ri] = As[ty * 8 + ri][kk];
#pragma unroll
            for (int g = 0; g < 4; g++)
#pragma unroll
                for (int ci = 0; ci < 2; ci++)
                    bb[g * 2 + ci] = Bsm[g * 32 + tx + 16 * ci][kk];
#pragma unroll
            for (int ri = 0; ri < 8; ri++)
#pragma unroll
                for (int j = 0; j < 8; j++) acc[ri][j] += a[ri] * bb[j];
        }
        __syncthreads();
    }
    // epilogue: LSTM pointwise
#pragma unroll
    for (int ri = 0; ri < 8; ri++) {
        int r = ty * 8 + ri;
        int n = n0 + r;
        float inpv = Inps[r];
#pragma unroll
        for (int ci = 0; ci < 2; ci++) {
            int cg = cb * 32 + tx + 16 * ci;
            float iv = acc[ri][0 * 2 + ci] + inpv * w_ih[cg]       + b_ih[cg]       + b_hh[cg];
            float fv = acc[ri][1 * 2 + ci] + inpv * w_ih[128 + cg] + b_ih[128 + cg] + b_hh[128 + cg];
            float gv = acc[ri][2 * 2 + ci] + inpv * w_ih[256 + cg] + b_ih[256 + cg] + b_hh[256 + cg];
            float ov = acc[ri][3 * 2 + ci] + inpv * w_ih[384 + cg] + b_ih[384 + cg] + b_hh[384 + cg];
            float ig = 1.f / (1.f + expf(-iv));
            float fg = 1.f / (1.f + expf(-fv));
            float gg = tanhf(gv);
            float og = 1.f / (1.f + expf(-ov));
            float cn = fg * c[n * LH + cg] + ig * gg;
            c[n * LH + cg] = cn;
            hnext[n * LH + cg] = og * tanhf(cn);
        }
    }
}

// ---------------- final: policy 1x1 conv + softmax over actions + outputs ----
__global__ __launch_bounds__(256) void final_kernel(
    const float* __restrict__ h, const float* __restrict__ pw,
    float* __restrict__ logits, float* __restrict__ probs,
    float* __restrict__ hk) {
    __shared__ float Ws[32][129];
    __shared__ float rows[8][128];
    int tid = threadIdx.x;
    for (int i = tid; i < 32 * 128; i += 256) Ws[i >> 7][i & 127] = pw[i];
    int warp = tid >> 5, lane = tid & 31;
    int n = blockIdx.x * 8 + warp;
#pragma unroll
    for (int q = 0; q < 4; q++)
        rows[warp][lane + 32 * q] = h[n * LH + lane + 32 * q];
    __syncthreads();
    float s = 0.f;
#pragma unroll
    for (int cch = 0; cch < 128; cch++) s += Ws[lane][cch] * rows[warp][cch];
    // lane j = o*8 + a ; softmax over the 8-lane action group
    float m = s;
#pragma unroll
    for (int off = 4; off; off >>= 1)
        m = fmaxf(m, __shfl_xor_sync(0xffffffffu, m, off));
    float e = expf(s - m);
    float sum = e;
#pragma unroll
    for (int off = 4; off; off >>= 1)
        sum += __shfl_xor_sync(0xffffffffu, sum, off);
    float p = e / sum;
    int b = n >> 10, x = (n >> 5) & 31, y = n & 31;
    int o = lane >> 3, a = lane & 7;
    int ooff = (((b * 8 + a) * 4 + o) * 32 + y) * 32 + x;
    logits[ooff] = s;
    probs[ooff] = p;
#pragma unroll
    for (int q = 0; q < 4; q++) {
        int cch = lane + 32 * q;
        hk[((b * 128 + cch) * 32 + y) * 32 + x] = rows[warp][cch];
    }
}

// ---------------- launcher ----------------------------------------------------
extern "C" void kernel_launch(void* const* d_in, const int* in_sizes, int n_in,
                              void* d_out, int out_size) {
    const float* design = (const float*)d_in[0];
    const float* goal   = (const float*)d_in[1];
    const float* hid_w  = (const float*)d_in[2];
    const float* hid_b  = (const float*)d_in[3];
    const float* h0_w   = (const float*)d_in[4];
    const float* h0_b   = (const float*)d_in[5];
    const float* c0_w   = (const float*)d_in[6];
    const float* c0_b   = (const float*)d_in[7];
    const float* conv_w = (const float*)d_in[8];
    const float* conv_b = (const float*)d_in[9];
    const float* w_ih   = (const float*)d_in[10];
    const float* w_hh   = (const float*)d_in[11];
    const float* b_ih   = (const float*)d_in[12];
    const float* b_hh   = (const float*)d_in[13];
    const float* pol_w  = (const float*)d_in[14];
    float* out = (float*)d_out;

    float *hid, *hA, *hB, *cbuf, *wth0, *wtc0;
    cudaGetSymbolAddress((void**)&hid,  g_hid);
    cudaGetSymbolAddress((void**)&hA,   g_hA);
    cudaGetSymbolAddress((void**)&hB,   g_hB);
    cudaGetSymbolAddress((void**)&cbuf, g_c);
    cudaGetSymbolAddress((void**)&wth0, g_wth0);
    cudaGetSymbolAddress((void**)&wtc0, g_wtc0);

    float* out_logits = out;
    float* out_probs  = out + 1048576;
    float* out_h0     = out + 2097152;
    float* out_hk     = out + 6291456;

    prep_weights<<<(9 * LH * LH + 255) / 256, 256>>>(h0_w, c0_w);
    hid_kernel<<<32, 256>>>(design, goal, hid_w, hid_b, hid);
    conv_gemm_kernel<<<NR / 128, 256>>>(hid, wth0, h0_b, hA, out_h0);
    conv_gemm_kernel<<<NR / 128, 256>>>(hid, wtc0, c0_b, cbuf, nullptr);

    float* cur = hA;
    float* nxt = hB;
    for (int t = 0; t < NSTEPS; t++) {
        step_kernel<<<dim3(NR / 128, 4), 256>>>(cur, w_hh, w_ih, b_ih, b_hh,
                                                conv_w, conv_b, cbuf, nxt);
        float* tmp = cur; cur = nxt; nxt = tmp;
    }
    final_kernel<<<NR / 8, 256>>>(cur, pol_w, out_logits, out_probs, out_hk);
}

// round 4
// speedup vs baseline: 1.0077x; 1.0077x over previous
#include <cuda_runtime.h>
#include <math.h>

#define NR 32768          // B*M*M = 32*32*32 rows
#define LH 128
#define NSTEPS 19         // K-1

// ---------------- scratch (static device globals; no allocation) -------------
__device__ float g_hid[NR * LH];      // hid conv output, flat [n][ci]
__device__ float g_hA[NR * LH];       // h ping
__device__ float g_hB[NR * LH];       // h pong
__device__ float g_c[NR * LH];        // c (in-place)
__device__ float g_wth0[9 * LH * LH]; // h0_w transposed [tap][ci][co]
__device__ float g_wtc0[9 * LH * LH]; // c0_w transposed [tap][ci][co]

// ---------------- weight transpose prep --------------------------------------
__global__ void prep_weights(const float* __restrict__ h0w,
                             const float* __restrict__ c0w) {
    int idx = blockIdx.x * 256 + threadIdx.x;   // idx = (tap*128+ci)*128+co
    if (idx >= 9 * LH * LH) return;
    int co  = idx & (LH - 1);
    int ci  = (idx >> 7) & (LH - 1);
    int tap = idx >> 14;
    int dy = tap / 3, dx = tap % 3;
    int src = ((co * LH + ci) * 3 + dy) * 3 + dx;
    g_wth0[idx] = h0w[src];
    g_wtc0[idx] = c0w[src];
}

// ---------------- initial hid conv: (design,goal) -> hid ----------------------
// hid_flat[n][co] with n = b*1024 + x*32 + y   (x = W index, y = H index)
__global__ __launch_bounds__(256) void hid_kernel(
    const float* __restrict__ design, const float* __restrict__ goal,
    const float* __restrict__ hid_w, const float* __restrict__ hid_b,
    float* __restrict__ out) {
    __shared__ float Xs[5][34][34];   // zero-padded input image
    __shared__ float Ws[128 * 45];
    __shared__ float Bs[128];
    int b = blockIdx.x;
    int tid = threadIdx.x;
    for (int i = tid; i < 5 * 34 * 34; i += 256) ((float*)Xs)[i] = 0.f;
    __syncthreads();
    for (int i = tid; i < 5 * 1024; i += 256) {
        int ci = i >> 10, y = (i >> 5) & 31, x = i & 31;
        float v = (ci < 4) ? design[((b * 4 + ci) * 32 + y) * 32 + x]
                           : goal[b * 1024 + y * 32 + x];
        Xs[ci][y + 1][x + 1] = v;
    }
    for (int i = tid; i < 128 * 45; i += 256) Ws[i] = hid_w[i];
    if (tid < 128) Bs[tid] = hid_b[tid];
    __syncthreads();
    for (int idx = tid; idx < 1024 * 128; idx += 256) {
        int co = idx & 127, p = idx >> 7;
        int x = p >> 5, y = p & 31;
        float s = Bs[co];
        const float* w = &Ws[co * 45];
#pragma unroll
        for (int ci = 0; ci < 5; ci++)
#pragma unroll
            for (int dy = 0; dy < 3; dy++)
#pragma unroll
                for (int dx = 0; dx < 3; dx++)
                    s += w[ci * 9 + dy * 3 + dx] * Xs[ci][y + dy][x + dx];
        out[(b * 1024 + p) * LH + co] = s;
    }
}

// ---------------- 3x3 conv as 9-tap GEMM (h0 / c0) ---------------------------
// out[n][co] = bias[co] + sum_taps sum_ci wt[tap][ci][co] * in[n+off(tap)][ci]
__global__ __launch_bounds__(256, 2) void conv_gemm_kernel(
    const float* __restrict__ in, const float* __restrict__ wt,
    const float* __restrict__ bias, float* __restrict__ out,
    float* __restrict__ out2) {
    __shared__ float As[128][33];
    __shared__ float Bsm[128][33];
    int n0 = blockIdx.x * 128;
    int tid = threadIdx.x;
    int tx = tid & 15, ty = tid >> 4;
    float acc[8][8];
#pragma unroll
    for (int i = 0; i < 8; i++)
#pragma unroll
        for (int j = 0; j < 8; j++) acc[i][j] = 0.f;

    for (int tap = 0; tap < 9; tap++) {
        int dy = tap / 3 - 1, dx = tap % 3 - 1;
        int off = dx * 32 + dy;
        for (int kc = 0; kc < LH; kc += 32) {
#pragma unroll
            for (int p = 0; p < 16; p++) {
                int i = tid + p * 256;
                int r = i >> 5, kk = i & 31;
                int n = n0 + r;
                int y = n & 31, x = (n >> 5) & 31;
                bool ok = ((unsigned)(y + dy) < 32u) && ((unsigned)(x + dx) < 32u);
                As[r][kk] = ok ? in[(n + off) * LH + kc + kk] : 0.f;
            }
#pragma unroll
            for (int p = 0; p < 16; p++) {
                int i = tid + p * 256;
                int kk = i >> 7, co = i & 127;
                Bsm[co][kk] = wt[(tap * LH + kc + kk) * LH + co];
            }
            __syncthreads();
#pragma unroll
            for (int kk = 0; kk < 32; kk++) {
                float a[8], bb[8];
#pragma unroll
                for (int ri = 0; ri < 8; ri++) a[ri] = As[ty * 8 + ri][kk];
#pragma unroll
                for (int j = 0; j < 8; j++) bb[j] = Bsm[tx + 16 * j][kk];
#pragma unroll
                for (int ri = 0; ri < 8; ri++)
#pragma unroll
                    for (int j = 0; j < 8; j++) acc[ri][j] += a[ri] * bb[j];
            }
            __syncthreads();
        }
    }
#pragma unroll
    for (int ri = 0; ri < 8; ri++) {
        int n = n0 + ty * 8 + ri;
#pragma unroll
        for (int j = 0; j < 8; j++) {
            int co = tx + 16 * j;
            float v = acc[ri][j] + bias[co];
            out[n * LH + co] = v;
            if (out2) out2[n * LH + co] = v;
        }
    }
}

// ---------------- fused: inp conv + gates GEMM + LSTM update -----------------
// Block tile: 128 rows x (4 gates x 32 channels). cb = channel chunk (0..3).
// inp[n] (the 128->1 3x3 conv on hprev) is computed in-block into smem.
__global__ __launch_bounds__(256, 2) void step_kernel(
    const float* __restrict__ hprev,
    const float* __restrict__ w_hh, const float* __restrict__ w_ih,
    const float* __restrict__ b_ih, const float* __restrict__ b_hh,
    const float* __restrict__ conv_w, const float* __restrict__ conv_b,
    float* __restrict__ c, float* __restrict__ hnext) {
    __shared__ float As[128][33];
    __shared__ float Bsm[128][33];
    __shared__ float Inps[128];
    int n0 = blockIdx.x * 128;
    int cb = blockIdx.y;
    int tid = threadIdx.x;
    int tx = tid & 15, ty = tid >> 4;

    // ---- compute inp for the block's 128 rows: 16 rows per warp (8 warps)
    {
        int warp = tid >> 5, lane = tid & 31;
#pragma unroll
        for (int rr = 0; rr < 16; rr++) {
            int r = warp * 16 + rr;
            int n = n0 + r;
            int y = n & 31, x = (n >> 5) & 31;
            float s = 0.f;
#pragma unroll
            for (int dy = 0; dy < 3; dy++)
#pragma unroll
                for (int dx = 0; dx < 3; dx++) {
                    int yy = y + dy - 1, xx = x + dx - 1;
                    if ((unsigned)yy < 32u && (unsigned)xx < 32u) {
                        const float* row = hprev + (n + (dx - 1) * 32 + (dy - 1)) * LH;
#pragma unroll
                        for (int q = 0; q < 4; q++) {
                            int ch = lane + q * 32;
                            s += conv_w[ch * 9 + dy * 3 + dx] * row[ch];
                        }
                    }
                }
#pragma unroll
            for (int off = 16; off; off >>= 1)
                s += __shfl_xor_sync(0xffffffffu, s, off);
            if (lane == 0) Inps[r] = s + conv_b[0];
        }
    }

    float acc[8][8];
#pragma unroll
    for (int i = 0; i < 8; i++)
#pragma unroll
        for (int j = 0; j < 8; j++) acc[i][j] = 0.f;

    for (int kc = 0; kc < LH; kc += 32) {
#pragma unroll
        for (int p = 0; p < 16; p++) {
            int i = tid + p * 256;
            int r = i >> 5, kk = i & 31;
            As[r][kk] = hprev[(n0 + r) * LH + kc + kk];
        }
#pragma unroll
        for (int p = 0; p < 16; p++) {
            int i = tid + p * 256;
            int jj = i >> 5, kk = i & 31;       // jj = gate*32 + c_loc
            int j = (jj >> 5) * 128 + cb * 32 + (jj & 31);
            Bsm[jj][kk] = w_hh[j * LH + kc + kk];
        }
        __syncthreads();
#pragma unroll
        for (int kk = 0; kk < 32; kk++) {
            float a[8], bb[8];
#pragma unroll
            for (int ri = 0; ri < 8; ri++) a[ri] = As[ty * 8 + ri][kk];
#pragma unroll
            for (int g = 0; g < 4; g++)
#pragma unroll
                for (int ci = 0; ci < 2; ci++)
                    bb[g * 2 + ci] = Bsm[g * 32 + tx + 16 * ci][kk];
#pragma unroll
            for (int ri = 0; ri < 8; ri++)
#pragma unroll
                for (int j = 0; j < 8; j++) acc[ri][j] += a[ri] * bb[j];
        }
        __syncthreads();
    }
    // epilogue: LSTM pointwise
#pragma unroll
    for (int ri = 0; ri < 8; ri++) {
        int r = ty * 8 + ri;
        int n = n0 + r;
        float inpv = Inps[r];
#pragma unroll
        for (int ci = 0; ci < 2; ci++) {
            int cg = cb * 32 + tx + 16 * ci;
            float iv = acc[ri][0 * 2 + ci] + inpv * w_ih[cg]       + b_ih[cg]       + b_hh[cg];
            float fv = acc[ri][1 * 2 + ci] + inpv * w_ih[128 + cg] + b_ih[128 + cg] + b_hh[128 + cg];
            float gv = acc[ri][2 * 2 + ci] + inpv * w_ih[256 + cg] + b_ih[256 + cg] + b_hh[256 + cg];
            float ov = acc[ri][3 * 2 + ci] + inpv * w_ih[384 + cg] + b_ih[384 + cg] + b_hh[384 + cg];
            float ig = 1.f / (1.f + expf(-iv));
            float fg = 1.f / (1.f + expf(-fv));
            float gg = tanhf(gv);
            float og = 1.f / (1.f + expf(-ov));
            float cn = fg * c[n * LH + cg] + ig * gg;
            c[n * LH + cg] = cn;
            hnext[n * LH + cg] = og * tanhf(cn);
        }
    }
}

// ---------------- final: policy 1x1 conv + softmax over actions + outputs ----
__global__ __launch_bounds__(256) void final_kernel(
    const float* __restrict__ h, const float* __restrict__ pw,
    float* __restrict__ logits, float* __restrict__ probs,
    float* __restrict__ hk) {
    __shared__ float Ws[32][129];
    __shared__ float rows[8][128];
    int tid = threadIdx.x;
    for (int i = tid; i < 32 * 128; i += 256) Ws[i >> 7][i & 127] = pw[i];
    int warp = tid >> 5, lane = tid & 31;
    int n = blockIdx.x * 8 + warp;
#pragma unroll
    for (int q = 0; q < 4; q++)
        rows[warp][lane + 32 * q] = h[n * LH + lane + 32 * q];
    __syncthreads();
    float s = 0.f;
#pragma unroll
    for (int cch = 0; cch < 128; cch++) s += Ws[lane][cch] * rows[warp][cch];
    // lane j = o*8 + a ; softmax over the 8-lane action group
    float m = s;
#pragma unroll
    for (int off = 4; off; off >>= 1)
        m = fmaxf(m, __shfl_xor_sync(0xffffffffu, m, off));
    float e = expf(s - m);
    float sum = e;
#pragma unroll
    for (int off = 4; off; off >>= 1)
        sum += __shfl_xor_sync(0xffffffffu, sum, off);
    float p = e / sum;
    int b = n >> 10, x = (n >> 5) & 31, y = n & 31;
    int o = lane >> 3, a = lane & 7;
    int ooff = (((b * 8 + a) * 4 + o) * 32 + y) * 32 + x;
    logits[ooff] = s;
    probs[ooff] = p;
#pragma unroll
    for (int q = 0; q < 4; q++) {
        int cch = lane + 32 * q;
        hk[((b * 128 + cch) * 32 + y) * 32 + x] = rows[warp][cch];
    }
}

// ---------------- launcher ----------------------------------------------------
extern "C" void kernel_launch(void* const* d_in, const int* in_sizes, int n_in,
                              void* d_out, int out_size) {
    const float* design = (const float*)d_in[0];
    const float* goal   = (const float*)d_in[1];
    const float* hid_w  = (const float*)d_in[2];
    const float* hid_b  = (const float*)d_in[3];
    const float* h0_w   = (const float*)d_in[4];
    const float* h0_b   = (const float*)d_in[5];
    const float* c0_w   = (const float*)d_in[6];
    const float* c0_b   = (const float*)d_in[7];
    const float* conv_w = (const float*)d_in[8];
    const float* conv_b = (const float*)d_in[9];
    const float* w_ih   = (const float*)d_in[10];
    const float* w_hh   = (const float*)d_in[11];
    const float* b_ih   = (const float*)d_in[12];
    const float* b_hh   = (const float*)d_in[13];
    const float* pol_w  = (const float*)d_in[14];
    float* out = (float*)d_out;

    float *hid, *hA, *hB, *cbuf, *wth0, *wtc0;
    cudaGetSymbolAddress((void**)&hid,  g_hid);
    cudaGetSymbolAddress((void**)&hA,   g_hA);
    cudaGetSymbolAddress((void**)&hB,   g_hB);
    cudaGetSymbolAddress((void**)&cbuf, g_c);
    cudaGetSymbolAddress((void**)&wth0, g_wth0);
    cudaGetSymbolAddress((void**)&wtc0, g_wtc0);

    float* out_logits = out;
    float* out_probs  = out + 1048576;
    float* out_h0     = out + 2097152;
    float* out_hk     = out + 6291456;

    prep_weights<<<(9 * LH * LH + 255) / 256, 256>>>(h0_w, c0_w);
    hid_kernel<<<32, 256>>>(design, goal, hid_w, hid_b, hid);
    conv_gemm_kernel<<<NR / 128, 256>>>(hid, wth0, h0_b, hA, out_h0);
    conv_gemm_kernel<<<NR / 128, 256>>>(hid, wtc0, c0_b, cbuf, nullptr);

    float* cur = hA;
    float* nxt = hB;
    for (int t = 0; t < NSTEPS; t++) {
        step_kernel<<<dim3(NR / 128, 4), 256>>>(cur, w_hh, w_ih, b_ih, b_hh,
                                                conv_w, conv_b, cbuf, nxt);
        float* tmp = cur; cur = nxt; nxt = tmp;
    }
    final_kernel<<<NR / 8, 256>>>(cur, pol_w, out_logits, out_probs, out_hk);
}

// round 9
// speedup vs baseline: 1.4680x; 1.4568x over previous
#include <cuda_runtime.h>
#include <cuda_fp16.h>
#include <math.h>
#include <stdint.h>

#define NR 32768          // B*M*M rows
#define LH 128
#define NSTEPS 19

// ============================ scratch globals ================================
__device__ float g_hid[NR * LH];
__device__ float g_c[NR * LH];
__device__ __half g_hAhi[NR * LH];
__device__ __half g_hAlo[NR * LH];
__device__ __half g_hBhi[NR * LH];
__device__ __half g_hBlo[NR * LH];
__device__ float g_inpp[4 * NR];
__device__ float g_wth0[9 * LH * LH];
__device__ float g_wtc0[9 * LH * LH];
// pre-swizzled B images: [cb quarter][hi/lo][128 rows x 256B ldmatrix-swizzled]
__device__ __align__(16) unsigned char g_Bimg2[4][2][32768];

// ============================ mma helpers ====================================
__device__ __forceinline__ void ldsm_x4(uint32_t& r0, uint32_t& r1,
                                        uint32_t& r2, uint32_t& r3,
                                        uint32_t addr) {
    asm volatile("ldmatrix.sync.aligned.m8n8.x4.shared.b16 {%0,%1,%2,%3}, [%4];"
                 : "=r"(r0), "=r"(r1), "=r"(r2), "=r"(r3) : "r"(addr));
}
__device__ __forceinline__ void mma16816(float* d, const uint32_t* a,
                                         uint32_t b0, uint32_t b1) {
    asm volatile(
        "mma.sync.aligned.m16n8k16.row.col.f32.f16.f16.f32 "
        "{%0,%1,%2,%3}, {%4,%5,%6,%7}, {%8,%9}, {%0,%1,%2,%3};"
        : "+f"(d[0]), "+f"(d[1]), "+f"(d[2]), "+f"(d[3])
        : "r"(a[0]), "r"(a[1]), "r"(a[2]), "r"(a[3]), "r"(b0), "r"(b1));
}
__device__ __forceinline__ uint32_t smem_to_u32(const void* p) {
    uint32_t a;
    asm("{ .reg .u64 t; cvta.to.shared.u64 t, %1; cvt.u32.u64 %0, t; }"
        : "=r"(a) : "l"(p));
    return a;
}

// ============================ weight prep ====================================
__global__ void prep_weights(const float* __restrict__ h0w,
                             const float* __restrict__ c0w) {
    int idx = blockIdx.x * 256 + threadIdx.x;
    if (idx >= 9 * LH * LH) return;
    int co = idx & 127, ci = (idx >> 7) & 127, tap = idx >> 14;
    int dy = tap / 3, dx = tap % 3;
    int src = ((co * LH + ci) * 3 + dy) * 3 + dx;
    g_wth0[idx] = h0w[src];
    g_wtc0[idx] = c0w[src];
}

// B image: row jj (block col) = q*16 + gp*8 + chl*2 + gl
//   q = ch>>2 within quarter, chl = ch&3, gate = gp*2+gl
// byte offset = jj*256 + (((k>>3) ^ (jj&7))<<4) + (k&7)*2
__global__ void prep_B2(const float* __restrict__ w_hh) {
    int idx = blockIdx.x * 256 + threadIdx.x;   // 4*2*128*128 = 131072
    if (idx >= 131072) return;
    int k = idx & 127;
    int jj = (idx >> 7) & 127;
    int term = (idx >> 14) & 1;
    int cb = idx >> 15;
    int q = jj >> 4, gp = (jj >> 3) & 1, chl = (jj >> 1) & 3, gl = jj & 1;
    int ch = cb * 32 + q * 4 + chl;
    int gate = gp * 2 + gl;
    float v = w_hh[(gate * 128 + ch) * 128 + k];
    __half hi = __float2half(v);
    __half o = term ? __float2half(v - __half2float(hi)) : hi;
    uint32_t off = jj * 256 + ((((k >> 3) ^ (jj & 7)) << 4)) + (k & 7) * 2;
    *(__half*)&g_Bimg2[cb][term][off] = o;
}

// ============================ initial hid conv ===============================
__global__ __launch_bounds__(256) void hid_kernel(
    const float* __restrict__ design, const float* __restrict__ goal,
    const float* __restrict__ hid_w, const float* __restrict__ hid_b,
    float* __restrict__ out) {
    __shared__ float Xs[5][34][34];
    __shared__ float Ws[128 * 45];
    __shared__ float Bs[128];
    int b = blockIdx.x, tid = threadIdx.x;
    for (int i = tid; i < 5 * 34 * 34; i += 256) ((float*)Xs)[i] = 0.f;
    __syncthreads();
    for (int i = tid; i < 5 * 1024; i += 256) {
        int ci = i >> 10, y = (i >> 5) & 31, x = i & 31;
        float v = (ci < 4) ? design[((b * 4 + ci) * 32 + y) * 32 + x]
                           : goal[b * 1024 + y * 32 + x];
        Xs[ci][y + 1][x + 1] = v;
    }
    for (int i = tid; i < 128 * 45; i += 256) Ws[i] = hid_w[i];
    if (tid < 128) Bs[tid] = hid_b[tid];
    __syncthreads();
    for (int idx = tid; idx < 1024 * 128; idx += 256) {
        int co = idx & 127, p = idx >> 7;
        int x = p >> 5, y = p & 31;
        float s = Bs[co];
        const float* w = &Ws[co * 45];
#pragma unroll
        for (int ci = 0; ci < 5; ci++)
#pragma unroll
            for (int dy = 0; dy < 3; dy++)
#pragma unroll
                for (int dx = 0; dx < 3; dx++)
                    s += w[ci * 9 + dy * 3 + dx] * Xs[ci][y + dy][x + dx];
        out[(b * 1024 + p) * LH + co] = s;
    }
}

// ============================ h0/c0 conv-GEMM ================================
__global__ __launch_bounds__(256, 2) void conv_gemm_kernel(
    const float* __restrict__ in, const float* __restrict__ wt,
    const float* __restrict__ bias, float* __restrict__ out,
    __half* __restrict__ outhi, __half* __restrict__ outlo) {
    __shared__ float As[128][33];
    __shared__ float Bsm[128][33];
    int n0 = blockIdx.x * 128, tid = threadIdx.x;
    int tx = tid & 15, ty = tid >> 4;
    float acc[8][8];
#pragma unroll
    for (int i = 0; i < 8; i++)
#pragma unroll
        for (int j = 0; j < 8; j++) acc[i][j] = 0.f;
    for (int tap = 0; tap < 9; tap++) {
        int dy = tap / 3 - 1, dx = tap % 3 - 1;
        int off = dx * 32 + dy;
        for (int kc = 0; kc < LH; kc += 32) {
#pragma unroll
            for (int p = 0; p < 16; p++) {
                int i = tid + p * 256;
                int r = i >> 5, kk = i & 31;
                int n = n0 + r;
                int y = n & 31, x = (n >> 5) & 31;
                bool ok = ((unsigned)(y + dy) < 32u) && ((unsigned)(x + dx) < 32u);
                As[r][kk] = ok ? in[(n + off) * LH + kc + kk] : 0.f;
            }
#pragma unroll
            for (int p = 0; p < 16; p++) {
                int i = tid + p * 256;
                int kk = i >> 7, co = i & 127;
                Bsm[co][kk] = wt[(tap * LH + kc + kk) * LH + co];
            }
            __syncthreads();
#pragma unroll
            for (int kk = 0; kk < 32; kk++) {
                float a[8], bb[8];
#pragma unroll
                for (int ri = 0; ri < 8; ri++) a[ri] = As[ty * 8 + ri][kk];
#pragma unroll
                for (int j = 0; j < 8; j++) bb[j] = Bsm[tx + 16 * j][kk];
#pragma unroll
                for (int ri = 0; ri < 8; ri++)
#pragma unroll
                    for (int j = 0; j < 8; j++) acc[ri][j] += a[ri] * bb[j];
            }
            __syncthreads();
        }
    }
#pragma unroll
    for (int ri = 0; ri < 8; ri++) {
        int n = n0 + ty * 8 + ri;
#pragma unroll
        for (int j = 0; j < 8; j++) {
            int co = tx + 16 * j;
            float v = acc[ri][j] + bias[co];
            if (out) out[n * LH + co] = v;
            if (outhi) {
                __half hi = __float2half(v);
                outhi[n * LH + co] = hi;
                outlo[n * LH + co] = __float2half(v - __half2float(hi));
            }
        }
    }
}

// ============================ inp conv partials ==============================
__global__ __launch_bounds__(256) void inp_partial_kernel(
    const __half* __restrict__ hhi, const __half* __restrict__ hlo,
    const float* __restrict__ conv_w) {
    extern __shared__ float ips[];          // [1024][33]
    __shared__ float w_s[288];
    int b = blockIdx.x, cbk = blockIdx.y, tid = threadIdx.x;
    for (int i = tid; i < 288; i += 256) {   // FIX: 288 > blockDim, must loop
        int ch = i / 9, tap = i % 9;
        w_s[i] = conv_w[(cbk * 32 + ch) * 9 + tap];
    }
    for (int idx = tid; idx < 1024 * 32; idx += 256) {
        int pos = idx >> 5, chl = idx & 31;
        int a = (b * 1024 + pos) * LH + cbk * 32 + chl;
        ips[pos * 33 + chl] = __half2float(hhi[a]) + __half2float(hlo[a]);
    }
    __syncthreads();
    for (int pos = tid; pos < 1024; pos += 256) {
        int x = pos >> 5, y = pos & 31;
        float s = 0.f;
#pragma unroll
        for (int dy = -1; dy <= 1; dy++)
#pragma unroll
            for (int dx = -1; dx <= 1; dx++) {
                int yy = y + dy, xx = x + dx;
                if ((unsigned)yy < 32u && (unsigned)xx < 32u) {
                    int base = (pos + dx * 32 + dy) * 33;
                    int tap = (dy + 1) * 3 + (dx + 1);
#pragma unroll
                    for (int ch = 0; ch < 32; ch++)
                        s += w_s[ch * 9 + tap] * ips[base + ch];
                }
            }
        g_inpp[cbk * NR + b * 1024 + pos] = s;
    }
}

// ============================ mma.sync step kernel ===========================
// Block: 128 rows x 128 gate-cols (one channel quarter cb).
// smem: A hi/lo (2x32KB), B hi/lo (2x32KB), ldmatrix XOR-chunk swizzle.
#define SA_HI 0u
#define SA_LO 32768u
#define SB_HI 65536u
#define SB_LO 98304u
#define SM_INP 131072u
#define SM_WIH 131584u
#define SM_BIAS 132096u
#define SM_TOT 132608u

__global__ __launch_bounds__(256, 1) void step_kernel(
    const __half* __restrict__ hhi, const __half* __restrict__ hlo,
    const float* __restrict__ w_ih, const float* __restrict__ b_ih,
    const float* __restrict__ b_hh, const float* __restrict__ conv_b,
    float* __restrict__ c,
    __half* __restrict__ nhi, __half* __restrict__ nlo) {
    extern __shared__ char smem[];
    uint32_t sb = smem_to_u32(smem);
    int tid = threadIdx.x, wid = tid >> 5, lane = tid & 31;
    int n0 = blockIdx.x * 128;
    int cb = blockIdx.y;

    // ---- B: copy pre-swizzled image (hi 32KB + lo 32KB contiguous) ---------
    {
        const uint4* src = (const uint4*)g_Bimg2[cb];
        uint4* dst = (uint4*)(smem + SB_HI);
#pragma unroll
        for (int t = 0; t < 16; t++) dst[tid + t * 256] = src[tid + t * 256];
    }
    // ---- A: h rows -> XOR-chunk swizzled tiles ------------------------------
    {
#pragma unroll
        for (int t = 0; t < 16; t++) {
            int idx = tid + t * 256;          // 4096 uint4
            int tile = idx >> 11;             // 0=hi 1=lo
            int r = (idx >> 4) & 127;
            int ch4 = idx & 15;               // 16B chunk
            const uint4* row = (const uint4*)((tile ? hlo : hhi) + (uint64_t)(n0 + r) * LH);
            uint4 v = row[ch4];
            *(uint4*)(smem + (tile ? SA_LO : SA_HI) + r * 256 + ((ch4 ^ (r & 7)) << 4)) = v;
        }
    }
    // ---- stage inp / w_ih / bias -------------------------------------------
    float* inps = (float*)(smem + SM_INP);
    float* wih_s = (float*)(smem + SM_WIH);
    float* bias_s = (float*)(smem + SM_BIAS);
    if (tid < 128) {
        int n = n0 + tid;
        inps[tid] = g_inpp[n] + g_inpp[NR + n] + g_inpp[2 * NR + n] +
                    g_inpp[3 * NR + n] + conv_b[0];
        int gate = tid >> 5, chb = tid & 31;
        int j = gate * 128 + cb * 32 + chb;
        wih_s[tid] = w_ih[j];
        bias_s[tid] = b_ih[j] + b_hh[j];
    }
    __syncthreads();

    // ---- MMA: 3 passes (Ahi*Bhi, Ahi*Blo, Alo*Bhi) --------------------------
    int warp_m = wid & 3, warp_n = wid >> 2;
    float acc[2][8][4];
#pragma unroll
    for (int mi = 0; mi < 2; mi++)
#pragma unroll
        for (int f = 0; f < 8; f++)
#pragma unroll
            for (int u = 0; u < 4; u++) acc[mi][f][u] = 0.f;

    int mat = lane >> 3, rr = lane & 7;
    int csel = mat >> 1;
    int rowA0 = warp_m * 32 + (mat & 1) * 8 + rr;          // for mi tiles: +16*mi
    int rowB0 = warp_n * 64 + (mat & 1) * 8 + rr;          // for t tiles: +16*t

#pragma unroll
    for (int pass = 0; pass < 3; pass++) {
        uint32_t abase = sb + (pass < 2 ? SA_HI : SA_LO);
        uint32_t bbase = sb + (pass == 1 ? SB_LO : SB_HI);
#pragma unroll
        for (int ks = 0; ks < 8; ks++) {
            uint32_t a[2][4];
#pragma unroll
            for (int mi = 0; mi < 2; mi++) {
                int row = rowA0 + mi * 16;
                uint32_t addr = abase + row * 256 + (((ks * 2 + csel) ^ (row & 7)) << 4);
                ldsm_x4(a[mi][0], a[mi][1], a[mi][2], a[mi][3], addr);
            }
            uint32_t bf[8][2];
#pragma unroll
            for (int t = 0; t < 4; t++) {
                int row = rowB0 + t * 16;
                uint32_t addr = bbase + row * 256 + (((ks * 2 + csel) ^ (row & 7)) << 4);
                uint32_t r0, r1, r2, r3;
                ldsm_x4(r0, r1, r2, r3, addr);
                bf[t * 2 + 0][0] = r0; bf[t * 2 + 0][1] = r2;
                bf[t * 2 + 1][0] = r1; bf[t * 2 + 1][1] = r3;
            }
#pragma unroll
            for (int mi = 0; mi < 2; mi++)
#pragma unroll
                for (int f = 0; f < 8; f++)
                    mma16816(acc[mi][f], a[mi], bf[f][0], bf[f][1]);
        }
    }

    // ---- epilogue: LSTM pointwise, direct global ----------------------------
    int g = lane >> 2, tig = lane & 3;
#pragma unroll
    for (int mi = 0; mi < 2; mi++) {
#pragma unroll
        for (int rh = 0; rh < 2; rh++) {
            int r = warp_m * 32 + mi * 16 + rh * 8 + g;
            uint64_t n = n0 + r;
            float inpv = inps[r];
#pragma unroll
            for (int ql = 0; ql < 4; ql++) {
                int chb = (warp_n * 4 + ql) * 4 + tig;   // 0..31
                int ch = cb * 32 + chb;
                float iv = acc[mi][ql * 2 + 0][rh * 2 + 0] + inpv * wih_s[chb]       + bias_s[chb];
                float fv = acc[mi][ql * 2 + 0][rh * 2 + 1] + inpv * wih_s[32 + chb]  + bias_s[32 + chb];
                float gv = acc[mi][ql * 2 + 1][rh * 2 + 0] + inpv * wih_s[64 + chb]  + bias_s[64 + chb];
                float ov = acc[mi][ql * 2 + 1][rh * 2 + 1] + inpv * wih_s[96 + chb]  + bias_s[96 + chb];
                float ig = 1.f / (1.f + expf(-iv));
                float fg = 1.f / (1.f + expf(-fv));
                float gg = tanhf(gv);
                float og = 1.f / (1.f + expf(-ov));
                uint64_t ga = n * LH + ch;
                float cn = fg * c[ga] + ig * gg;
                c[ga] = cn;
                float hv = og * tanhf(cn);
                __half hi = __float2half(hv);
                nhi[ga] = hi;
                nlo[ga] = __float2half(hv - __half2float(hi));
            }
        }
    }
}

// ============================ final kernel ===================================
__global__ __launch_bounds__(256) void final_kernel(
    const __half* __restrict__ hhi, const __half* __restrict__ hlo,
    const float* __restrict__ pw,
    float* __restrict__ logits, float* __restrict__ probs,
    float* __restrict__ hk) {
    __shared__ float Ws[32][129];
    __shared__ float rows[8][128];
    int tid = threadIdx.x;
    for (int i = tid; i < 32 * 128; i += 256) Ws[i >> 7][i & 127] = pw[i];
    int warp = tid >> 5, lane = tid & 31;
    int n = blockIdx.x * 8 + warp;
#pragma unroll
    for (int q = 0; q < 4; q++) {
        int a = n * LH + lane + 32 * q;
        rows[warp][lane + 32 * q] = __half2float(hhi[a]) + __half2float(hlo[a]);
    }
    __syncthreads();
    float s = 0.f;
#pragma unroll
    for (int cch = 0; cch < 128; cch++) s += Ws[lane][cch] * rows[warp][cch];
    float m = s;
#pragma unroll
    for (int off = 4; off; off >>= 1)
        m = fmaxf(m, __shfl_xor_sync(0xffffffffu, m, off));
    float e = expf(s - m);
    float sum = e;
#pragma unroll
    for (int off = 4; off; off >>= 1)
        sum += __shfl_xor_sync(0xffffffffu, sum, off);
    float p = e / sum;
    int b = n >> 10, x = (n >> 5) & 31, y = n & 31;
    int o = lane >> 3, a = lane & 7;
    int ooff = (((b * 8 + a) * 4 + o) * 32 + y) * 32 + x;
    logits[ooff] = s;
    probs[ooff] = p;
#pragma unroll
    for (int q = 0; q < 4; q++) {
        int cch = lane + 32 * q;
        hk[((b * 128 + cch) * 32 + y) * 32 + x] = rows[warp][cch];
    }
}

// ============================ launcher =======================================
extern "C" void kernel_launch(void* const* d_in, const int* in_sizes, int n_in,
                              void* d_out, int out_size) {
    const float* design = (const float*)d_in[0];
    const float* goal   = (const float*)d_in[1];
    const float* hid_w  = (const float*)d_in[2];
    const float* hid_b  = (const float*)d_in[3];
    const float* h0_w   = (const float*)d_in[4];
    const float* h0_b   = (const float*)d_in[5];
    const float* c0_w   = (const float*)d_in[6];
    const float* c0_b   = (const float*)d_in[7];
    const float* conv_w = (const float*)d_in[8];
    const float* conv_b = (const float*)d_in[9];
    const float* w_ih   = (const float*)d_in[10];
    const float* w_hh   = (const float*)d_in[11];
    const float* b_ih   = (const float*)d_in[12];
    const float* b_hh   = (const float*)d_in[13];
    const float* pol_w  = (const float*)d_in[14];
    float* out = (float*)d_out;

    float *hid, *cbuf, *wth0, *wtc0;
    __half *hAhi, *hAlo, *hBhi, *hBlo;
    cudaGetSymbolAddress((void**)&hid,  g_hid);
    cudaGetSymbolAddress((void**)&cbuf, g_c);
    cudaGetSymbolAddress((void**)&wth0, g_wth0);
    cudaGetSymbolAddress((void**)&wtc0, g_wtc0);
    cudaGetSymbolAddress((void**)&hAhi, g_hAhi);
    cudaGetSymbolAddress((void**)&hAlo, g_hAlo);
    cudaGetSymbolAddress((void**)&hBhi, g_hBhi);
    cudaGetSymbolAddress((void**)&hBlo, g_hBlo);

    cudaFuncSetAttribute(step_kernel,
                         cudaFuncAttributeMaxDynamicSharedMemorySize, SM_TOT);
    cudaFuncSetAttribute(inp_partial_kernel,
                         cudaFuncAttributeMaxDynamicSharedMemorySize, 1024 * 33 * 4);

    float* out_logits = out;
    float* out_probs  = out + 1048576;
    float* out_h0     = out + 2097152;
    float* out_hk     = out + 6291456;

    prep_weights<<<(9 * LH * LH + 255) / 256, 256>>>(h0_w, c0_w);
    prep_B2<<<131072 / 256, 256>>>(w_hh);
    hid_kernel<<<32, 256>>>(design, goal, hid_w, hid_b, hid);
    conv_gemm_kernel<<<NR / 128, 256>>>(hid, wth0, h0_b, out_h0, hAhi, hAlo);
    conv_gemm_kernel<<<NR / 128, 256>>>(hid, wtc0, c0_b, cbuf, nullptr, nullptr);

    __half *curhi = hAhi, *curlo = hAlo, *nxthi = hBhi, *nxtlo = hBlo;
    for (int t = 0; t < NSTEPS; t++) {
        inp_partial_kernel<<<dim3(32, 4), 256, 1024 * 33 * 4>>>(curhi, curlo, conv_w);
        step_kernel<<<dim3(256, 4), 256, SM_TOT>>>(
            curhi, curlo, w_ih, b_ih, b_hh, conv_b, cbuf, nxthi, nxtlo);
        __half* t1 = curhi; curhi = nxthi; nxthi = t1;
        __half* t2 = curlo; curlo = nxtlo; nxtlo = t2;
    }
    final_kernel<<<NR / 8, 256>>>(curhi, curlo, pol_w, out_logits, out_probs, out_hk);
}

// round 10
// speedup vs baseline: 1.5399x; 1.0490x over previous
#include <cuda_runtime.h>
#include <cuda_fp16.h>
#include <math.h>
#include <stdint.h>

#define NR 32768          // B*M*M rows
#define LH 128
#define NSTEPS 19

// ============================ scratch globals ================================
__device__ float g_hid[NR * LH];
__device__ float g_c[NR * LH];
__device__ __half g_hAhi[NR * LH];
__device__ __half g_hAlo[NR * LH];
__device__ __half g_hBhi[NR * LH];
__device__ __half g_hBlo[NR * LH];
__device__ float g_inpp[4 * NR];
__device__ float g_wth0[9 * LH * LH];
__device__ float g_wtc0[9 * LH * LH];
// pre-swizzled B images: [col-block of 64 jj][hi/lo][64 rows x 256B swizzled]
__device__ __align__(16) unsigned char g_Bimg3[8][2][16384];

// ============================ mma helpers ====================================
__device__ __forceinline__ void ldsm_x4(uint32_t& r0, uint32_t& r1,
                                        uint32_t& r2, uint32_t& r3,
                                        uint32_t addr) {
    asm volatile("ldmatrix.sync.aligned.m8n8.x4.shared.b16 {%0,%1,%2,%3}, [%4];"
                 : "=r"(r0), "=r"(r1), "=r"(r2), "=r"(r3) : "r"(addr));
}
__device__ __forceinline__ void mma16816(float* d, const uint32_t* a,
                                         uint32_t b0, uint32_t b1) {
    asm volatile(
        "mma.sync.aligned.m16n8k16.row.col.f32.f16.f16.f32 "
        "{%0,%1,%2,%3}, {%4,%5,%6,%7}, {%8,%9}, {%0,%1,%2,%3};"
        : "+f"(d[0]), "+f"(d[1]), "+f"(d[2]), "+f"(d[3])
        : "r"(a[0]), "r"(a[1]), "r"(a[2]), "r"(a[3]), "r"(b0), "r"(b1));
}
__device__ __forceinline__ uint32_t smem_to_u32(const void* p) {
    uint32_t a;
    asm("{ .reg .u64 t; cvta.to.shared.u64 t, %1; cvt.u32.u64 %0, t; }"
        : "=r"(a) : "l"(p));
    return a;
}

// ============================ weight prep ====================================
__global__ void prep_weights(const float* __restrict__ h0w,
                             const float* __restrict__ c0w) {
    int idx = blockIdx.x * 256 + threadIdx.x;
    if (idx >= 9 * LH * LH) return;
    int co = idx & 127, ci = (idx >> 7) & 127, tap = idx >> 14;
    int dy = tap / 3, dx = tap % 3;
    int src = ((co * LH + ci) * 3 + dy) * 3 + dx;
    g_wth0[idx] = h0w[src];
    g_wtc0[idx] = c0w[src];
}

// B image: col-block cb (16 channels), row jj (0..63) = q*16 + gp*8 + chl*2 + gl
//   channel = cb*16 + q*4 + chl,  gate = gp*2 + gl
// byte offset = jj*256 + (((k>>3) ^ (jj&7))<<4) + (k&7)*2
__global__ void prep_B2(const float* __restrict__ w_hh) {
    int idx = blockIdx.x * 256 + threadIdx.x;   // 8*2*64*128 = 131072
    if (idx >= 131072) return;
    int k = idx & 127;
    int jj = (idx >> 7) & 63;
    int term = (idx >> 13) & 1;
    int cb = idx >> 14;
    int q = jj >> 4, gp = (jj >> 3) & 1, chl = (jj >> 1) & 3, gl = jj & 1;
    int ch = cb * 16 + q * 4 + chl;
    int gate = gp * 2 + gl;
    float v = w_hh[(gate * 128 + ch) * 128 + k];
    __half hi = __float2half(v);
    __half o = term ? __float2half(v - __half2float(hi)) : hi;
    uint32_t off = jj * 256 + ((((k >> 3) ^ (jj & 7)) << 4)) + (k & 7) * 2;
    *(__half*)&g_Bimg3[cb][term][off] = o;
}

// ============================ initial hid conv ===============================
__global__ __launch_bounds__(256) void hid_kernel(
    const float* __restrict__ design, const float* __restrict__ goal,
    const float* __restrict__ hid_w, const float* __restrict__ hid_b,
    float* __restrict__ out) {
    __shared__ float Xs[5][34][34];
    __shared__ float Ws[128 * 45];
    __shared__ float Bs[128];
    int b = blockIdx.x, tid = threadIdx.x;
    for (int i = tid; i < 5 * 34 * 34; i += 256) ((float*)Xs)[i] = 0.f;
    __syncthreads();
    for (int i = tid; i < 5 * 1024; i += 256) {
        int ci = i >> 10, y = (i >> 5) & 31, x = i & 31;
        float v = (ci < 4) ? design[((b * 4 + ci) * 32 + y) * 32 + x]
                           : goal[b * 1024 + y * 32 + x];
        Xs[ci][y + 1][x + 1] = v;
    }
    for (int i = tid; i < 128 * 45; i += 256) Ws[i] = hid_w[i];
    if (tid < 128) Bs[tid] = hid_b[tid];
    __syncthreads();
    for (int idx = tid; idx < 1024 * 128; idx += 256) {
        int co = idx & 127, p = idx >> 7;
        int x = p >> 5, y = p & 31;
        float s = Bs[co];
        const float* w = &Ws[co * 45];
#pragma unroll
        for (int ci = 0; ci < 5; ci++)
#pragma unroll
            for (int dy = 0; dy < 3; dy++)
#pragma unroll
                for (int dx = 0; dx < 3; dx++)
                    s += w[ci * 9 + dy * 3 + dx] * Xs[ci][y + dy][x + dx];
        out[(b * 1024 + p) * LH + co] = s;
    }
}

// ============================ h0/c0 conv-GEMM ================================
__global__ __launch_bounds__(256, 2) void conv_gemm_kernel(
    const float* __restrict__ in, const float* __restrict__ wt,
    const float* __restrict__ bias, float* __restrict__ out,
    __half* __restrict__ outhi, __half* __restrict__ outlo) {
    __shared__ float As[128][33];
    __shared__ float Bsm[128][33];
    int n0 = blockIdx.x * 128, tid = threadIdx.x;
    int tx = tid & 15, ty = tid >> 4;
    float acc[8][8];
#pragma unroll
    for (int i = 0; i < 8; i++)
#pragma unroll
        for (int j = 0; j < 8; j++) acc[i][j] = 0.f;
    for (int tap = 0; tap < 9; tap++) {
        int dy = tap / 3 - 1, dx = tap % 3 - 1;
        int off = dx * 32 + dy;
        for (int kc = 0; kc < LH; kc += 32) {
#pragma unroll
            for (int p = 0; p < 16; p++) {
                int i = tid + p * 256;
                int r = i >> 5, kk = i & 31;
                int n = n0 + r;
                int y = n & 31, x = (n >> 5) & 31;
                bool ok = ((unsigned)(y + dy) < 32u) && ((unsigned)(x + dx) < 32u);
                As[r][kk] = ok ? in[(n + off) * LH + kc + kk] : 0.f;
            }
#pragma unroll
            for (int p = 0; p < 16; p++) {
                int i = tid + p * 256;
                int kk = i >> 7, co = i & 127;
                Bsm[co][kk] = wt[(tap * LH + kc + kk) * LH + co];
            }
            __syncthreads();
#pragma unroll
            for (int kk = 0; kk < 32; kk++) {
                float a[8], bb[8];
#pragma unroll
                for (int ri = 0; ri < 8; ri++) a[ri] = As[ty * 8 + ri][kk];
#pragma unroll
                for (int j = 0; j < 8; j++) bb[j] = Bsm[tx + 16 * j][kk];
#pragma unroll
                for (int ri = 0; ri < 8; ri++)
#pragma unroll
                    for (int j = 0; j < 8; j++) acc[ri][j] += a[ri] * bb[j];
            }
            __syncthreads();
        }
    }
#pragma unroll
    for (int ri = 0; ri < 8; ri++) {
        int n = n0 + ty * 8 + ri;
#pragma unroll
        for (int j = 0; j < 8; j++) {
            int co = tx + 16 * j;
            float v = acc[ri][j] + bias[co];
            if (out) out[n * LH + co] = v;
            if (outhi) {
                __half hi = __float2half(v);
                outhi[n * LH + co] = hi;
                outlo[n * LH + co] = __float2half(v - __half2float(hi));
            }
        }
    }
}

// ============================ inp conv partials ==============================
__global__ __launch_bounds__(256) void inp_partial_kernel(
    const __half* __restrict__ hhi, const __half* __restrict__ hlo,
    const float* __restrict__ conv_w) {
    extern __shared__ float ips[];          // [1024][33]
    __shared__ float w_s[288];
    int b = blockIdx.x, cbk = blockIdx.y, tid = threadIdx.x;
    for (int i = tid; i < 288; i += 256) {
        int ch = i / 9, tap = i % 9;
        w_s[i] = conv_w[(cbk * 32 + ch) * 9 + tap];
    }
    for (int idx = tid; idx < 1024 * 32; idx += 256) {
        int pos = idx >> 5, chl = idx & 31;
        int a = (b * 1024 + pos) * LH + cbk * 32 + chl;
        ips[pos * 33 + chl] = __half2float(hhi[a]) + __half2float(hlo[a]);
    }
    __syncthreads();
    for (int pos = tid; pos < 1024; pos += 256) {
        int x = pos >> 5, y = pos & 31;
        float s = 0.f;
#pragma unroll
        for (int dy = -1; dy <= 1; dy++)
#pragma unroll
            for (int dx = -1; dx <= 1; dx++) {
                int yy = y + dy, xx = x + dx;
                if ((unsigned)yy < 32u && (unsigned)xx < 32u) {
                    int base = (pos + dx * 32 + dy) * 33;
                    int tap = (dy + 1) * 3 + (dx + 1);
#pragma unroll
                    for (int ch = 0; ch < 32; ch++)
                        s += w_s[ch * 9 + tap] * ips[base + ch];
                }
            }
        g_inpp[cbk * NR + b * 1024 + pos] = s;
    }
}

// ============================ mma.sync step kernel ===========================
// Block: 128 rows x 64 gate-cols (16 channels, col-block cb of 8).
// smem 97KB -> 2 blocks/SM. A hi/lo 64KB + B hi/lo 32KB, XOR-chunk swizzle.
#define SA_HI 0u
#define SA_LO 32768u
#define SB_HI 65536u
#define SB_LO 81920u
#define SM_INP 98304u
#define SM_WIH 98816u
#define SM_BIAS 99072u
#define SM_TOT 99328u

__global__ __launch_bounds__(256, 2) void step_kernel(
    const __half* __restrict__ hhi, const __half* __restrict__ hlo,
    const float* __restrict__ w_ih, const float* __restrict__ b_ih,
    const float* __restrict__ b_hh, const float* __restrict__ conv_b,
    float* __restrict__ c,
    __half* __restrict__ nhi, __half* __restrict__ nlo) {
    extern __shared__ char smem[];
    uint32_t sb = smem_to_u32(smem);
    int tid = threadIdx.x, wid = tid >> 5, lane = tid & 31;
    int n0 = blockIdx.x * 128;
    int cb = blockIdx.y;                    // 0..7 (16 channels each)

    // ---- B: copy pre-swizzled image (hi 16KB + lo 16KB contiguous) ---------
    {
        const uint4* src = (const uint4*)g_Bimg3[cb];
        uint4* dst = (uint4*)(smem + SB_HI);
#pragma unroll
        for (int t = 0; t < 8; t++) dst[tid + t * 256] = src[tid + t * 256];
    }
    // ---- A: h rows -> XOR-chunk swizzled tiles ------------------------------
    {
#pragma unroll
        for (int t = 0; t < 16; t++) {
            int idx = tid + t * 256;          // 4096 uint4
            int tile = idx >> 11;             // 0=hi 1=lo
            int r = (idx >> 4) & 127;
            int ch4 = idx & 15;               // 16B chunk
            const uint4* row = (const uint4*)((tile ? hlo : hhi) + (uint64_t)(n0 + r) * LH);
            uint4 v = row[ch4];
            *(uint4*)(smem + (tile ? SA_LO : SA_HI) + r * 256 + ((ch4 ^ (r & 7)) << 4)) = v;
        }
    }
    // ---- stage inp / w_ih / bias -------------------------------------------
    float* inps = (float*)(smem + SM_INP);
    float* wih_s = (float*)(smem + SM_WIH);      // [gate*16 + chb16]
    float* bias_s = (float*)(smem + SM_BIAS);
    if (tid < 128) {
        int n = n0 + tid;
        inps[tid] = g_inpp[n] + g_inpp[NR + n] + g_inpp[2 * NR + n] +
                    g_inpp[3 * NR + n] + conv_b[0];
    }
    if (tid < 64) {
        int gate = tid >> 4, chb = tid & 15;
        int j = gate * 128 + cb * 16 + chb;
        wih_s[tid] = w_ih[j];
        bias_s[tid] = b_ih[j] + b_hh[j];
    }
    __syncthreads();

    // ---- MMA: 3 passes (Ahi*Bhi, Ahi*Blo, Alo*Bhi) --------------------------
    int warp_m = wid & 3, warp_n = wid >> 2;     // warp_n 0..1 (32 jj each)
    float acc[2][4][4];
#pragma unroll
    for (int mi = 0; mi < 2; mi++)
#pragma unroll
        for (int f = 0; f < 4; f++)
#pragma unroll
            for (int u = 0; u < 4; u++) acc[mi][f][u] = 0.f;

    int mat = lane >> 3, rr = lane & 7;
    int csel = mat >> 1;
    int rowA0 = warp_m * 32 + (mat & 1) * 8 + rr;      // mi tiles: +16*mi
    int rowB0 = warp_n * 32 + (mat & 1) * 8 + rr;      // t tiles: +16*t

#pragma unroll
    for (int pass = 0; pass < 3; pass++) {
        uint32_t abase = sb + (pass < 2 ? SA_HI : SA_LO);
        uint32_t bbase = sb + (pass == 1 ? SB_LO : SB_HI);
#pragma unroll
        for (int ks = 0; ks < 8; ks++) {
            uint32_t a[2][4];
#pragma unroll
            for (int mi = 0; mi < 2; mi++) {
                int row = rowA0 + mi * 16;
                uint32_t addr = abase + row * 256 + (((ks * 2 + csel) ^ (row & 7)) << 4);
                ldsm_x4(a[mi][0], a[mi][1], a[mi][2], a[mi][3], addr);
            }
            uint32_t bf[4][2];
#pragma unroll
            for (int t = 0; t < 2; t++) {
                int row = rowB0 + t * 16;
                uint32_t addr = bbase + row * 256 + (((ks * 2 + csel) ^ (row & 7)) << 4);
                uint32_t r0, r1, r2, r3;
                ldsm_x4(r0, r1, r2, r3, addr);
                bf[t * 2 + 0][0] = r0; bf[t * 2 + 0][1] = r2;
                bf[t * 2 + 1][0] = r1; bf[t * 2 + 1][1] = r3;
            }
#pragma unroll
            for (int mi = 0; mi < 2; mi++)
#pragma unroll
                for (int f = 0; f < 4; f++)
                    mma16816(acc[mi][f], a[mi], bf[f][0], bf[f][1]);
        }
    }

    // ---- epilogue: LSTM pointwise, direct global ----------------------------
    // f group covers jj = warp_n*32 + (f>>1)*16 + (f&1)*8 : q = warp_n*2+(f>>1), gp = f&1
    int g = lane >> 2, tig = lane & 3;
#pragma unroll
    for (int mi = 0; mi < 2; mi++) {
#pragma unroll
        for (int rh = 0; rh < 2; rh++) {
            int r = warp_m * 32 + mi * 16 + rh * 8 + g;
            uint64_t n = n0 + r;
            float inpv = inps[r];
#pragma unroll
            for (int qq = 0; qq < 2; qq++) {
                int chb = (warp_n * 2 + qq) * 4 + tig;   // 0..15
                int ch = cb * 16 + chb;
                float iv = acc[mi][qq * 2 + 0][rh * 2 + 0] + inpv * wih_s[chb]      + bias_s[chb];
                float fv = acc[mi][qq * 2 + 0][rh * 2 + 1] + inpv * wih_s[16 + chb] + bias_s[16 + chb];
                float gv = acc[mi][qq * 2 + 1][rh * 2 + 0] + inpv * wih_s[32 + chb] + bias_s[32 + chb];
                float ov = acc[mi][qq * 2 + 1][rh * 2 + 1] + inpv * wih_s[48 + chb] + bias_s[48 + chb];
                float ig = 1.f / (1.f + expf(-iv));
                float fg = 1.f / (1.f + expf(-fv));
                float gg = tanhf(gv);
                float og = 1.f / (1.f + expf(-ov));
                uint64_t ga = n * LH + ch;
                float cn = fg * c[ga] + ig * gg;
                c[ga] = cn;
                float hv = og * tanhf(cn);
                __half hi = __float2half(hv);
                nhi[ga] = hi;
                nlo[ga] = __float2half(hv - __half2float(hi));
            }
        }
    }
}

// ============================ final kernel ===================================
__global__ __launch_bounds__(256) void final_kernel(
    const __half* __restrict__ hhi, const __half* __restrict__ hlo,
    const float* __restrict__ pw,
    float* __restrict__ logits, float* __restrict__ probs,
    float* __restrict__ hk) {
    __shared__ float Ws[32][129];
    __shared__ float rows[8][128];
    int tid = threadIdx.x;
    for (int i = tid; i < 32 * 128; i += 256) Ws[i >> 7][i & 127] = pw[i];
    int warp = tid >> 5, lane = tid & 31;
    int n = blockIdx.x * 8 + warp;
#pragma unroll
    for (int q = 0; q < 4; q++) {
        int a = n * LH + lane + 32 * q;
        rows[warp][lane + 32 * q] = __half2float(hhi[a]) + __half2float(hlo[a]);
    }
    __syncthreads();
    float s = 0.f;
#pragma unroll
    for (int cch = 0; cch < 128; cch++) s += Ws[lane][cch] * rows[warp][cch];
    float m = s;
#pragma unroll
    for (int off = 4; off; off >>= 1)
        m = fmaxf(m, __shfl_xor_sync(0xffffffffu, m, off));
    float e = expf(s - m);
    float sum = e;
#pragma unroll
    for (int off = 4; off; off >>= 1)
        sum += __shfl_xor_sync(0xffffffffu, sum, off);
    float p = e / sum;
    int b = n >> 10, x = (n >> 5) & 31, y = n & 31;
    int o = lane >> 3, a = lane & 7;
    int ooff = (((b * 8 + a) * 4 + o) * 32 + y) * 32 + x;
    logits[ooff] = s;
    probs[ooff] = p;
#pragma unroll
    for (int q = 0; q < 4; q++) {
        int cch = lane + 32 * q;
        hk[((b * 128 + cch) * 32 + y) * 32 + x] = rows[warp][cch];
    }
}

// ============================ launcher =======================================
extern "C" void kernel_launch(void* const* d_in, const int* in_sizes, int n_in,
                              void* d_out, int out_size) {
    const float* design = (const float*)d_in[0];
    const float* goal   = (const float*)d_in[1];
    const float* hid_w  = (const float*)d_in[2];
    const float* hid_b  = (const float*)d_in[3];
    const float* h0_w   = (const float*)d_in[4];
    const float* h0_b   = (const float*)d_in[5];
    const float* c0_w   = (const float*)d_in[6];
    const float* c0_b   = (const float*)d_in[7];
    const float* conv_w = (const float*)d_in[8];
    const float* conv_b = (const float*)d_in[9];
    const float* w_ih   = (const float*)d_in[10];
    const float* w_hh   = (const float*)d_in[11];
    const float* b_ih   = (const float*)d_in[12];
    const float* b_hh   = (const float*)d_in[13];
    const float* pol_w  = (const float*)d_in[14];
    float* out = (float*)d_out;

    float *hid, *cbuf, *wth0, *wtc0;
    __half *hAhi, *hAlo, *hBhi, *hBlo;
    cudaGetSymbolAddress((void**)&hid,  g_hid);
    cudaGetSymbolAddress((void**)&cbuf, g_c);
    cudaGetSymbolAddress((void**)&wth0, g_wth0);
    cudaGetSymbolAddress((void**)&wtc0, g_wtc0);
    cudaGetSymbolAddress((void**)&hAhi, g_hAhi);
    cudaGetSymbolAddress((void**)&hAlo, g_hAlo);
    cudaGetSymbolAddress((void**)&hBhi, g_hBhi);
    cudaGetSymbolAddress((void**)&hBlo, g_hBlo);

    cudaFuncSetAttribute(step_kernel,
                         cudaFuncAttributeMaxDynamicSharedMemorySize, SM_TOT);
    cudaFuncSetAttribute(inp_partial_kernel,
                         cudaFuncAttributeMaxDynamicSharedMemorySize, 1024 * 33 * 4);

    float* out_logits = out;
    float* out_probs  = out + 1048576;
    float* out_h0     = out + 2097152;
    float* out_hk     = out + 6291456;

    prep_weights<<<(9 * LH * LH + 255) / 256, 256>>>(h0_w, c0_w);
    prep_B2<<<131072 / 256, 256>>>(w_hh);
    hid_kernel<<<32, 256>>>(design, goal, hid_w, hid_b, hid);
    conv_gemm_kernel<<<NR / 128, 256>>>(hid, wth0, h0_b, out_h0, hAhi, hAlo);
    conv_gemm_kernel<<<NR / 128, 256>>>(hid, wtc0, c0_b, cbuf, nullptr, nullptr);

    __half *curhi = hAhi, *curlo = hAlo, *nxthi = hBhi, *nxtlo = hBlo;
    for (int t = 0; t < NSTEPS; t++) {
        inp_partial_kernel<<<dim3(32, 4), 256, 1024 * 33 * 4>>>(curhi, curlo, conv_w);
        step_kernel<<<dim3(256, 8), 256, SM_TOT>>>(
            curhi, curlo, w_ih, b_ih, b_hh, conv_b, cbuf, nxthi, nxtlo);
        __half* t1 = curhi; curhi = nxthi; nxthi = t1;
        __half* t2 = curlo; curlo = nxtlo; nxtlo = t2;
    }
    final_kernel<<<NR / 8, 256>>>(curhi, curlo, pol_w, out_logits, out_probs, out_hk);
}